// round 6
// baseline (speedup 1.0000x reference)
#include <cuda_runtime.h>
#include <cuda_fp16.h>
#include <cstdint>

// ---------------- problem constants ----------------
#define T 2048
#define H 1024
#define E 8
#define TOPK 2
#define F 4096
#define NSLOT (T*TOPK)
#define LN_EPS 1e-5f
#define GATE_EPS 1e-8f

// ---------------- scratch ----------------
__device__ __half g_XN[(size_t)T * H];        // 4 MB  normalized tokens, fp16
__device__ __half g_ACT[(size_t)NSLOT * F];   // 32 MB g*silu(u), fp16
__device__ float  g_Y[(size_t)NSLOT * H];     // 16 MB expert outputs
__device__ int   g_cnt[E];
__device__ int   g_off[E];
__device__ int   g_tok_e[T*TOPK];
__device__ int   g_tok_p[T*TOPK];
__device__ float g_tok_w[T*TOPK];
__device__ int   g_tok_slot[T*TOPK];
__device__ int   g_slot_tok[NSLOT];

// ---------------- k0 ----------------
__global__ void k_zero() {
    if (threadIdx.x < E) g_cnt[threadIdx.x] = 0;
}

// ---------------- k1: layernorm + router ----------------
__global__ void __launch_bounds__(256) k_router(
    const float* __restrict__ x, const float* __restrict__ lnw,
    const float* __restrict__ lnb, const float* __restrict__ gw)
{
    int t = blockIdx.x, tid = threadIdx.x;
    int lane = tid & 31, wid = tid >> 5;
    const float* xr = x + (size_t)t * H;

    float v[4];
    float s = 0.f, s2 = 0.f;
#pragma unroll
    for (int i = 0; i < 4; i++) {
        float a = xr[tid + i * 256];
        v[i] = a; s += a; s2 += a * a;
    }
    __shared__ float sw[8], sw2[8], stat[2];
#pragma unroll
    for (int o = 16; o > 0; o >>= 1) {
        s  += __shfl_down_sync(0xffffffffu, s,  o);
        s2 += __shfl_down_sync(0xffffffffu, s2, o);
    }
    if (lane == 0) { sw[wid] = s; sw2[wid] = s2; }
    __syncthreads();
    if (wid == 0) {
        float a = (lane < 8) ? sw[lane]  : 0.f;
        float b = (lane < 8) ? sw2[lane] : 0.f;
#pragma unroll
        for (int o = 4; o > 0; o >>= 1) {
            a += __shfl_down_sync(0xffffffffu, a, o);
            b += __shfl_down_sync(0xffffffffu, b, o);
        }
        if (lane == 0) {
            float mean = a / (float)H;
            float var  = b / (float)H - mean * mean;
            stat[0] = mean;
            stat[1] = rsqrtf(var + LN_EPS);
        }
    }
    __syncthreads();
    float mean = stat[0], rstd = stat[1];

    float part[E];
#pragma unroll
    for (int e = 0; e < E; e++) part[e] = 0.f;
#pragma unroll
    for (int i = 0; i < 4; i++) {
        int h = tid + i * 256;
        float xn = (v[i] - mean) * rstd * lnw[h] + lnb[h];
        g_XN[(size_t)t * H + h] = __float2half_rn(xn);
#pragma unroll
        for (int e = 0; e < E; e++) part[e] += xn * gw[e * H + h];
    }
    __shared__ float pl[8 * E];
#pragma unroll
    for (int e = 0; e < E; e++) {
        float p = part[e];
#pragma unroll
        for (int o = 16; o > 0; o >>= 1) p += __shfl_down_sync(0xffffffffu, p, o);
        if (lane == 0) pl[wid * E + e] = p;
    }
    __syncthreads();
    if (tid == 0) {
        float lg[E];
#pragma unroll
        for (int e = 0; e < E; e++) {
            float acc = 0.f;
            for (int w = 0; w < 8; w++) acc += pl[w * E + e];
            lg[e] = acc;
        }
        float m = lg[0];
#pragma unroll
        for (int e = 1; e < E; e++) m = fmaxf(m, lg[e]);
        float p[E], den = 0.f;
#pragma unroll
        for (int e = 0; e < E; e++) { p[e] = expf(lg[e] - m); den += p[e]; }
#pragma unroll
        for (int e = 0; e < E; e++) p[e] /= den;
        int e0 = 0;
#pragma unroll
        for (int e = 1; e < E; e++) if (p[e] > p[e0]) e0 = e;
        int e1 = -1;
#pragma unroll
        for (int e = 0; e < E; e++) {
            if (e == e0) continue;
            if (e1 < 0 || p[e] > p[e1]) e1 = e;
        }
        float g0 = p[e0], g1 = p[e1];
        float gs = g0 + g1 + GATE_EPS;
        g0 /= gs; g1 /= gs;
        int p0 = atomicAdd(&g_cnt[e0], 1);
        int p1 = atomicAdd(&g_cnt[e1], 1);
        g_tok_e[t*2]   = e0; g_tok_e[t*2+1] = e1;
        g_tok_p[t*2]   = p0; g_tok_p[t*2+1] = p1;
        g_tok_w[t*2]   = g0; g_tok_w[t*2+1] = g1;
    }
}

// ---------------- k2: scan + aux loss ----------------
__global__ void k_scan(float* __restrict__ out, int out_size) {
    if (threadIdx.x == 0 && blockIdx.x == 0) {
        int off = 0;
        int c[E];
        for (int e = 0; e < E; e++) { c[e] = g_cnt[e]; g_off[e] = off; off += c[e]; }
        double tot = (double)off;
        double u[E], mean = 0.0;
        for (int e = 0; e < E; e++) { u[e] = (double)c[e] / tot; mean += u[e]; }
        mean /= (double)E;
        double var = 0.0;
        for (int e = 0; e < E; e++) { double d = u[e] - mean; var += d * d; }
        var /= (double)(E - 1);
        double lbl = var / (mean + 1e-8);
        lbl = lbl * lbl;
        if (out_size > T * H) out[T * H] = (float)lbl;
    }
}

// ---------------- k3: slot assignment ----------------
__global__ void k_assign() {
    int i = blockIdx.x * blockDim.x + threadIdx.x;
    if (i >= T * TOPK) return;
    int e = g_tok_e[i];
    int slot = g_off[e] + g_tok_p[i];
    g_tok_slot[i] = slot;
    g_slot_tok[slot] = i >> 1;
}

// ---------------- mma helper (fp16 in, fp32 accum) ----------------
__device__ __forceinline__ void mma16816(float* c, const uint32_t* a, uint32_t b0, uint32_t b1) {
    asm volatile(
        "mma.sync.aligned.m16n8k16.row.col.f32.f16.f16.f32 "
        "{%0,%1,%2,%3}, {%4,%5,%6,%7}, {%8,%9}, {%0,%1,%2,%3};\n"
        : "+f"(c[0]), "+f"(c[1]), "+f"(c[2]), "+f"(c[3])
        : "r"(a[0]), "r"(a[1]), "r"(a[2]), "r"(a[3]), "r"(b0), "r"(b1));
}

#define BM 128
#define BK 32
#define SPITCH 40

// ---------------- k4: GEMM1 fused SwiGLU ----------------
// A[128 rows from XN fp16] x B[128 interleaved cols: even=Wg f-col, odd=Wu f-col] (fp16)
// Epilogue: act = g * silu(u) in fp32 -> fp16 ACT.
// Grid: x = M-tile (fastest -> weight tile L2 reuse), y = col-tile, z = expert.
__global__ void __launch_bounds__(256, 2) k_gemmA(
    const float* __restrict__ Wg, const float* __restrict__ Wu)
{
    int e = blockIdx.z;
    int n_e = g_cnt[e];
    int rows0 = blockIdx.x * BM;
    if (rows0 >= n_e) return;
    int off = g_off[e];
    int mrows = min(BM, n_e - rows0);
    int col0 = blockIdx.y * 64;   // f-column base
    int tid = threadIdx.x;

    __shared__ __half As[BM * SPITCH];
    __shared__ __half Bs[128 * SPITCH];

    const __half* aptr[2];
    int asmo[2];
#pragma unroll
    for (int it = 0; it < 2; it++) {
        int idx = tid + it * 256;
        int row = idx >> 2, seg = idx & 3;
        asmo[it] = row * SPITCH + seg * 8;
        if (row < mrows) {
            int tok = g_slot_tok[off + rows0 + row];
            aptr[it] = g_XN + (size_t)tok * H + seg * 8;
        } else aptr[it] = nullptr;
    }
    const float* bptr[4];
    int bsmo[4];
#pragma unroll
    for (int it = 0; it < 4; it++) {
        int idx = tid + it * 256;
        int row = idx >> 3, seg = idx & 7;
        bsmo[it] = row * SPITCH + seg * 4;
        int fc = col0 + (row >> 1);
        const float* base = (row & 1) ? Wu : Wg;
        bptr[it] = base + ((size_t)e * F + fc) * (size_t)H + seg * 4;
    }

    int wid = tid >> 5, lane = tid & 31;
    int wm = wid & 3, wn = wid >> 2;
    int grp = lane >> 2, tg = lane & 3;

    float acc[2][8][4];
#pragma unroll
    for (int mt = 0; mt < 2; mt++)
#pragma unroll
        for (int nt = 0; nt < 8; nt++)
#pragma unroll
            for (int q = 0; q < 4; q++) acc[mt][nt][q] = 0.f;

    uint4 areg[2];
    float4 breg[4];
#pragma unroll
    for (int it = 0; it < 2; it++)
        areg[it] = aptr[it] ? *(const uint4*)(aptr[it]) : make_uint4(0u,0u,0u,0u);
#pragma unroll
    for (int it = 0; it < 4; it++)
        breg[it] = *(const float4*)(bptr[it]);

    for (int kk = 0; kk < H; kk += BK) {
        __syncthreads();
#pragma unroll
        for (int it = 0; it < 2; it++)
            *(uint4*)&As[asmo[it]] = areg[it];
#pragma unroll
        for (int it = 0; it < 4; it++) {
            float4 f = breg[it];
            __half2 lo = __floats2half2_rn(f.x, f.y);
            __half2 hi = __floats2half2_rn(f.z, f.w);
            *(__half2*)&Bs[bsmo[it]]     = lo;
            *(__half2*)&Bs[bsmo[it] + 2] = hi;
        }
        __syncthreads();
        if (kk + BK < H) {
#pragma unroll
            for (int it = 0; it < 2; it++)
                areg[it] = aptr[it] ? *(const uint4*)(aptr[it] + kk + BK) : make_uint4(0u,0u,0u,0u);
#pragma unroll
            for (int it = 0; it < 4; it++)
                breg[it] = *(const float4*)(bptr[it] + kk + BK);
        }
#pragma unroll
        for (int ks = 0; ks < BK; ks += 16) {
            uint32_t afr[2][4];
#pragma unroll
            for (int mt = 0; mt < 2; mt++) {
                int rb = wm * 32 + mt * 16;
                afr[mt][0] = *(const uint32_t*)&As[(rb + grp) * SPITCH + ks + tg * 2];
                afr[mt][1] = *(const uint32_t*)&As[(rb + grp + 8) * SPITCH + ks + tg * 2];
                afr[mt][2] = *(const uint32_t*)&As[(rb + grp) * SPITCH + ks + tg * 2 + 8];
                afr[mt][3] = *(const uint32_t*)&As[(rb + grp + 8) * SPITCH + ks + tg * 2 + 8];
            }
#pragma unroll
            for (int nt = 0; nt < 8; nt++) {
                int baddr = (wn * 64 + nt * 8 + grp) * SPITCH + ks + tg * 2;
                uint32_t b0 = *(const uint32_t*)&Bs[baddr];
                uint32_t b1 = *(const uint32_t*)&Bs[baddr + 8];
                mma16816(acc[0][nt], afr[0], b0, b1);
                mma16816(acc[1][nt], afr[1], b0, b1);
            }
        }
    }

    // epilogue: act = g * silu(u); (c0,c1)=(g,u) row r0; (c2,c3)=(g,u) row r1
#pragma unroll
    for (int mt = 0; mt < 2; mt++) {
        int r0 = wm * 32 + mt * 16 + grp;
        int r1 = r0 + 8;
#pragma unroll
        for (int nt = 0; nt < 8; nt++) {
            int j = col0 + wn * 32 + nt * 4 + tg;
            float gv = acc[mt][nt][0], uv = acc[mt][nt][1];
            if (r0 < mrows)
                g_ACT[(size_t)(off + rows0 + r0) * F + j] =
                    __float2half_rn(gv * (uv / (1.f + expf(-uv))));
            gv = acc[mt][nt][2]; uv = acc[mt][nt][3];
            if (r1 < mrows)
                g_ACT[(size_t)(off + rows0 + r1) * F + j] =
                    __float2half_rn(gv * (uv / (1.f + expf(-uv))));
        }
    }
}

// ---------------- k6: GEMM2  [n_e,F] x Wd[H,F]^T -> Y fp32 ----------------
__global__ void __launch_bounds__(256, 2) k_gemmB(const float* __restrict__ Wd) {
    int e = blockIdx.z;
    int n_e = g_cnt[e];
    int rows0 = blockIdx.x * BM;
    if (rows0 >= n_e) return;
    int off = g_off[e];
    int mrows = min(BM, n_e - rows0);
    int col0 = blockIdx.y * 128;   // H columns
    int tid = threadIdx.x;

    __shared__ __half As[BM * SPITCH];
    __shared__ __half Bs[128 * SPITCH];

    const __half* aptr[2];
    int asmo[2];
#pragma unroll
    for (int it = 0; it < 2; it++) {
        int idx = tid + it * 256;
        int row = idx >> 2, seg = idx & 3;
        asmo[it] = row * SPITCH + seg * 8;
        if (row < mrows)
            aptr[it] = g_ACT + (size_t)(off + rows0 + row) * F + seg * 8;
        else aptr[it] = nullptr;
    }
    const float* bptr[4];
    int bsmo[4];
#pragma unroll
    for (int it = 0; it < 4; it++) {
        int idx = tid + it * 256;
        int row = idx >> 3, seg = idx & 7;
        bsmo[it] = row * SPITCH + seg * 4;
        int h = col0 + row;
        bptr[it] = Wd + ((size_t)e * H + h) * (size_t)F + seg * 4;
    }

    int wid = tid >> 5, lane = tid & 31;
    int wm = wid & 3, wn = wid >> 2;
    int grp = lane >> 2, tg = lane & 3;

    float acc[2][8][4];
#pragma unroll
    for (int mt = 0; mt < 2; mt++)
#pragma unroll
        for (int nt = 0; nt < 8; nt++)
#pragma unroll
            for (int q = 0; q < 4; q++) acc[mt][nt][q] = 0.f;

    uint4 areg[2];
    float4 breg[4];
#pragma unroll
    for (int it = 0; it < 2; it++)
        areg[it] = aptr[it] ? *(const uint4*)(aptr[it]) : make_uint4(0u,0u,0u,0u);
#pragma unroll
    for (int it = 0; it < 4; it++)
        breg[it] = *(const float4*)(bptr[it]);

    for (int kk = 0; kk < F; kk += BK) {
        __syncthreads();
#pragma unroll
        for (int it = 0; it < 2; it++)
            *(uint4*)&As[asmo[it]] = areg[it];
#pragma unroll
        for (int it = 0; it < 4; it++) {
            float4 f = breg[it];
            __half2 lo = __floats2half2_rn(f.x, f.y);
            __half2 hi = __floats2half2_rn(f.z, f.w);
            *(__half2*)&Bs[bsmo[it]]     = lo;
            *(__half2*)&Bs[bsmo[it] + 2] = hi;
        }
        __syncthreads();
        if (kk + BK < F) {
#pragma unroll
            for (int it = 0; it < 2; it++)
                areg[it] = aptr[it] ? *(const uint4*)(aptr[it] + kk + BK) : make_uint4(0u,0u,0u,0u);
#pragma unroll
            for (int it = 0; it < 4; it++)
                breg[it] = *(const float4*)(bptr[it] + kk + BK);
        }
#pragma unroll
        for (int ks = 0; ks < BK; ks += 16) {
            uint32_t afr[2][4];
#pragma unroll
            for (int mt = 0; mt < 2; mt++) {
                int rb = wm * 32 + mt * 16;
                afr[mt][0] = *(const uint32_t*)&As[(rb + grp) * SPITCH + ks + tg * 2];
                afr[mt][1] = *(const uint32_t*)&As[(rb + grp + 8) * SPITCH + ks + tg * 2];
                afr[mt][2] = *(const uint32_t*)&As[(rb + grp) * SPITCH + ks + tg * 2 + 8];
                afr[mt][3] = *(const uint32_t*)&As[(rb + grp + 8) * SPITCH + ks + tg * 2 + 8];
            }
#pragma unroll
            for (int nt = 0; nt < 8; nt++) {
                int baddr = (wn * 64 + nt * 8 + grp) * SPITCH + ks + tg * 2;
                uint32_t b0 = *(const uint32_t*)&Bs[baddr];
                uint32_t b1 = *(const uint32_t*)&Bs[baddr + 8];
                mma16816(acc[0][nt], afr[0], b0, b1);
                mma16816(acc[1][nt], afr[1], b0, b1);
            }
        }
    }
#pragma unroll
    for (int mt = 0; mt < 2; mt++) {
        int r0l = wm * 32 + mt * 16 + grp;
        int r1l = r0l + 8;
#pragma unroll
        for (int nt = 0; nt < 8; nt++) {
            int j = col0 + wn * 64 + nt * 8 + tg * 2;
            if (r0l < mrows) {
                float2 o = make_float2(acc[mt][nt][0], acc[mt][nt][1]);
                *(float2*)&g_Y[(size_t)(off + rows0 + r0l) * H + j] = o;
            }
            if (r1l < mrows) {
                float2 o = make_float2(acc[mt][nt][2], acc[mt][nt][3]);
                *(float2*)&g_Y[(size_t)(off + rows0 + r1l) * H + j] = o;
            }
        }
    }
}

// ---------------- k7: combine + residual ----------------
__global__ void __launch_bounds__(256) k_combine(
    const float* __restrict__ x, float* __restrict__ out)
{
    int t = blockIdx.x, tid = threadIdx.x;
    int s0 = g_tok_slot[t * 2], s1 = g_tok_slot[t * 2 + 1];
    float w0 = g_tok_w[t * 2], w1 = g_tok_w[t * 2 + 1];
    const float4* xv = (const float4*)(x + (size_t)t * H);
    const float4* y0 = (const float4*)(g_Y + (size_t)s0 * H);
    const float4* y1 = (const float4*)(g_Y + (size_t)s1 * H);
    float4* ov = (float4*)(out + (size_t)t * H);
    float4 a = xv[tid], b = y0[tid], c = y1[tid];
    float4 r;
    r.x = a.x + w0 * b.x + w1 * c.x;
    r.y = a.y + w0 * b.y + w1 * c.y;
    r.z = a.z + w0 * b.z + w1 * c.z;
    r.w = a.w + w0 * b.w + w1 * c.w;
    ov[tid] = r;
}

// ---------------- launch ----------------
extern "C" void kernel_launch(void* const* d_in, const int* in_sizes, int n_in,
                              void* d_out, int out_size)
{
    const float* x    = (const float*)d_in[0];
    const float* lnw  = (const float*)d_in[1];
    const float* lnb  = (const float*)d_in[2];
    const float* gw   = (const float*)d_in[3];
    const float* Wg   = (const float*)d_in[4];
    const float* Wu   = (const float*)d_in[5];
    const float* Wd   = (const float*)d_in[6];
    float* out = (float*)d_out;

    k_zero<<<1, 32>>>();
    k_router<<<T, 256>>>(x, lnw, lnb, gw);
    k_scan<<<1, 32>>>(out, out_size);
    k_assign<<<(T * TOPK + 255) / 256, 256>>>();

    // M-tile fastest (blockIdx.x) -> all M-blocks of one weight tile in-flight together
    dim3 gA((T + BM - 1) / BM, F / 64, E);   // (16,64,8)
    k_gemmA<<<gA, 256>>>(Wg, Wu);

    dim3 gB((T + BM - 1) / BM, H / 128, E);  // (16,8,8)
    k_gemmB<<<gB, 256>>>(Wd);

    k_combine<<<T, 256>>>(x, out);
}

// round 7
// speedup vs baseline: 1.0038x; 1.0038x over previous
#include <cuda_runtime.h>
#include <cuda_fp16.h>
#include <cstdint>

// ---------------- problem constants ----------------
#define T 2048
#define H 1024
#define E 8
#define TOPK 2
#define F 4096
#define NSLOT (T*TOPK)
#define LN_EPS 1e-5f
#define GATE_EPS 1e-8f

// ---------------- scratch ----------------
__device__ __half g_XN[(size_t)T * H];        // 4 MB  normalized tokens, fp16
__device__ __half g_ACT[(size_t)NSLOT * F];   // 32 MB g*silu(u), fp16
__device__ float  g_Y[(size_t)NSLOT * H];     // 16 MB expert outputs
__device__ int   g_cnt[E];
__device__ int   g_off[E];
__device__ int   g_tok_e[T*TOPK];
__device__ int   g_tok_p[T*TOPK];
__device__ float g_tok_w[T*TOPK];
__device__ int   g_tok_slot[T*TOPK];
__device__ int   g_slot_tok[NSLOT];

// ---------------- k0 ----------------
__global__ void k_zero() {
    if (threadIdx.x < E) g_cnt[threadIdx.x] = 0;
}

// ---------------- k1: layernorm + router ----------------
__global__ void __launch_bounds__(256) k_router(
    const float* __restrict__ x, const float* __restrict__ lnw,
    const float* __restrict__ lnb, const float* __restrict__ gw)
{
    int t = blockIdx.x, tid = threadIdx.x;
    int lane = tid & 31, wid = tid >> 5;
    const float* xr = x + (size_t)t * H;

    float v[4];
    float s = 0.f, s2 = 0.f;
#pragma unroll
    for (int i = 0; i < 4; i++) {
        float a = xr[tid + i * 256];
        v[i] = a; s += a; s2 += a * a;
    }
    __shared__ float sw[8], sw2[8], stat[2];
#pragma unroll
    for (int o = 16; o > 0; o >>= 1) {
        s  += __shfl_down_sync(0xffffffffu, s,  o);
        s2 += __shfl_down_sync(0xffffffffu, s2, o);
    }
    if (lane == 0) { sw[wid] = s; sw2[wid] = s2; }
    __syncthreads();
    if (wid == 0) {
        float a = (lane < 8) ? sw[lane]  : 0.f;
        float b = (lane < 8) ? sw2[lane] : 0.f;
#pragma unroll
        for (int o = 4; o > 0; o >>= 1) {
            a += __shfl_down_sync(0xffffffffu, a, o);
            b += __shfl_down_sync(0xffffffffu, b, o);
        }
        if (lane == 0) {
            float mean = a / (float)H;
            float var  = b / (float)H - mean * mean;
            stat[0] = mean;
            stat[1] = rsqrtf(var + LN_EPS);
        }
    }
    __syncthreads();
    float mean = stat[0], rstd = stat[1];

    float part[E];
#pragma unroll
    for (int e = 0; e < E; e++) part[e] = 0.f;
#pragma unroll
    for (int i = 0; i < 4; i++) {
        int h = tid + i * 256;
        float xn = (v[i] - mean) * rstd * lnw[h] + lnb[h];
        g_XN[(size_t)t * H + h] = __float2half_rn(xn);
#pragma unroll
        for (int e = 0; e < E; e++) part[e] += xn * gw[e * H + h];
    }
    __shared__ float pl[8 * E];
#pragma unroll
    for (int e = 0; e < E; e++) {
        float p = part[e];
#pragma unroll
        for (int o = 16; o > 0; o >>= 1) p += __shfl_down_sync(0xffffffffu, p, o);
        if (lane == 0) pl[wid * E + e] = p;
    }
    __syncthreads();
    if (tid == 0) {
        float lg[E];
#pragma unroll
        for (int e = 0; e < E; e++) {
            float acc = 0.f;
            for (int w = 0; w < 8; w++) acc += pl[w * E + e];
            lg[e] = acc;
        }
        float m = lg[0];
#pragma unroll
        for (int e = 1; e < E; e++) m = fmaxf(m, lg[e]);
        float p[E], den = 0.f;
#pragma unroll
        for (int e = 0; e < E; e++) { p[e] = expf(lg[e] - m); den += p[e]; }
#pragma unroll
        for (int e = 0; e < E; e++) p[e] /= den;
        int e0 = 0;
#pragma unroll
        for (int e = 1; e < E; e++) if (p[e] > p[e0]) e0 = e;
        int e1 = -1;
#pragma unroll
        for (int e = 0; e < E; e++) {
            if (e == e0) continue;
            if (e1 < 0 || p[e] > p[e1]) e1 = e;
        }
        float g0 = p[e0], g1 = p[e1];
        float gs = g0 + g1 + GATE_EPS;
        g0 /= gs; g1 /= gs;
        int p0 = atomicAdd(&g_cnt[e0], 1);
        int p1 = atomicAdd(&g_cnt[e1], 1);
        g_tok_e[t*2]   = e0; g_tok_e[t*2+1] = e1;
        g_tok_p[t*2]   = p0; g_tok_p[t*2+1] = p1;
        g_tok_w[t*2]   = g0; g_tok_w[t*2+1] = g1;
    }
}

// ---------------- k2: scan + aux loss ----------------
__global__ void k_scan(float* __restrict__ out, int out_size) {
    if (threadIdx.x == 0 && blockIdx.x == 0) {
        int off = 0;
        int c[E];
        for (int e = 0; e < E; e++) { c[e] = g_cnt[e]; g_off[e] = off; off += c[e]; }
        double tot = (double)off;
        double u[E], mean = 0.0;
        for (int e = 0; e < E; e++) { u[e] = (double)c[e] / tot; mean += u[e]; }
        mean /= (double)E;
        double var = 0.0;
        for (int e = 0; e < E; e++) { double d = u[e] - mean; var += d * d; }
        var /= (double)(E - 1);
        double lbl = var / (mean + 1e-8);
        lbl = lbl * lbl;
        if (out_size > T * H) out[T * H] = (float)lbl;
    }
}

// ---------------- k3: slot assignment ----------------
__global__ void k_assign() {
    int i = blockIdx.x * blockDim.x + threadIdx.x;
    if (i >= T * TOPK) return;
    int e = g_tok_e[i];
    int slot = g_off[e] + g_tok_p[i];
    g_tok_slot[i] = slot;
    g_slot_tok[slot] = i >> 1;
}

// ---------------- mma helper (fp16 in, fp32 accum) ----------------
__device__ __forceinline__ void mma16816(float* c, const uint32_t* a, uint32_t b0, uint32_t b1) {
    asm volatile(
        "mma.sync.aligned.m16n8k16.row.col.f32.f16.f16.f32 "
        "{%0,%1,%2,%3}, {%4,%5,%6,%7}, {%8,%9}, {%0,%1,%2,%3};\n"
        : "+f"(c[0]), "+f"(c[1]), "+f"(c[2]), "+f"(c[3])
        : "r"(a[0]), "r"(a[1]), "r"(a[2]), "r"(a[3]), "r"(b0), "r"(b1));
}

#define BM 128
#define BK 32
#define SPITCH 40

// ---------------- k4: GEMM1 fused SwiGLU ----------------
// A[128 rows from XN fp16] x B[128 interleaved cols: even=Wg f-col, odd=Wu f-col] (fp16)
// Epilogue: act = g * silu(u) in fp32 -> fp16 ACT.
// Grid: x = M-tile (fastest -> weight tile L2 reuse), y = col-tile, z = expert.
__global__ void __launch_bounds__(256, 2) k_gemmA(
    const float* __restrict__ Wg, const float* __restrict__ Wu)
{
    int e = blockIdx.z;
    int n_e = g_cnt[e];
    int rows0 = blockIdx.x * BM;
    if (rows0 >= n_e) return;
    int off = g_off[e];
    int mrows = min(BM, n_e - rows0);
    int col0 = blockIdx.y * 64;   // f-column base
    int tid = threadIdx.x;

    __shared__ __half As[BM * SPITCH];
    __shared__ __half Bs[128 * SPITCH];

    const __half* aptr[2];
    int asmo[2];
#pragma unroll
    for (int it = 0; it < 2; it++) {
        int idx = tid + it * 256;
        int row = idx >> 2, seg = idx & 3;
        asmo[it] = row * SPITCH + seg * 8;
        if (row < mrows) {
            int tok = g_slot_tok[off + rows0 + row];
            aptr[it] = g_XN + (size_t)tok * H + seg * 8;
        } else aptr[it] = nullptr;
    }
    const float* bptr[4];
    int bsmo[4];
#pragma unroll
    for (int it = 0; it < 4; it++) {
        int idx = tid + it * 256;
        int row = idx >> 3, seg = idx & 7;
        bsmo[it] = row * SPITCH + seg * 4;
        int fc = col0 + (row >> 1);
        const float* base = (row & 1) ? Wu : Wg;
        bptr[it] = base + ((size_t)e * F + fc) * (size_t)H + seg * 4;
    }

    int wid = tid >> 5, lane = tid & 31;
    int wm = wid & 3, wn = wid >> 2;
    int grp = lane >> 2, tg = lane & 3;

    float acc[2][8][4];
#pragma unroll
    for (int mt = 0; mt < 2; mt++)
#pragma unroll
        for (int nt = 0; nt < 8; nt++)
#pragma unroll
            for (int q = 0; q < 4; q++) acc[mt][nt][q] = 0.f;

    uint4 areg[2];
    float4 breg[4];
#pragma unroll
    for (int it = 0; it < 2; it++)
        areg[it] = aptr[it] ? *(const uint4*)(aptr[it]) : make_uint4(0u,0u,0u,0u);
#pragma unroll
    for (int it = 0; it < 4; it++)
        breg[it] = *(const float4*)(bptr[it]);

    for (int kk = 0; kk < H; kk += BK) {
        __syncthreads();
#pragma unroll
        for (int it = 0; it < 2; it++)
            *(uint4*)&As[asmo[it]] = areg[it];
#pragma unroll
        for (int it = 0; it < 4; it++) {
            float4 f = breg[it];
            __half2 lo = __floats2half2_rn(f.x, f.y);
            __half2 hi = __floats2half2_rn(f.z, f.w);
            *(__half2*)&Bs[bsmo[it]]     = lo;
            *(__half2*)&Bs[bsmo[it] + 2] = hi;
        }
        __syncthreads();
        if (kk + BK < H) {
#pragma unroll
            for (int it = 0; it < 2; it++)
                areg[it] = aptr[it] ? *(const uint4*)(aptr[it] + kk + BK) : make_uint4(0u,0u,0u,0u);
#pragma unroll
            for (int it = 0; it < 4; it++)
                breg[it] = *(const float4*)(bptr[it] + kk + BK);
        }
#pragma unroll
        for (int ks = 0; ks < BK; ks += 16) {
            uint32_t afr[2][4];
#pragma unroll
            for (int mt = 0; mt < 2; mt++) {
                int rb = wm * 32 + mt * 16;
                afr[mt][0] = *(const uint32_t*)&As[(rb + grp) * SPITCH + ks + tg * 2];
                afr[mt][1] = *(const uint32_t*)&As[(rb + grp + 8) * SPITCH + ks + tg * 2];
                afr[mt][2] = *(const uint32_t*)&As[(rb + grp) * SPITCH + ks + tg * 2 + 8];
                afr[mt][3] = *(const uint32_t*)&As[(rb + grp + 8) * SPITCH + ks + tg * 2 + 8];
            }
#pragma unroll
            for (int nt = 0; nt < 8; nt++) {
                int baddr = (wn * 64 + nt * 8 + grp) * SPITCH + ks + tg * 2;
                uint32_t b0 = *(const uint32_t*)&Bs[baddr];
                uint32_t b1 = *(const uint32_t*)&Bs[baddr + 8];
                mma16816(acc[0][nt], afr[0], b0, b1);
                mma16816(acc[1][nt], afr[1], b0, b1);
            }
        }
    }

    // epilogue: act = g * silu(u); (c0,c1)=(g,u) row r0; (c2,c3)=(g,u) row r1
#pragma unroll
    for (int mt = 0; mt < 2; mt++) {
        int r0 = wm * 32 + mt * 16 + grp;
        int r1 = r0 + 8;
#pragma unroll
        for (int nt = 0; nt < 8; nt++) {
            int j = col0 + wn * 32 + nt * 4 + tg;
            float gv = acc[mt][nt][0], uv = acc[mt][nt][1];
            if (r0 < mrows)
                g_ACT[(size_t)(off + rows0 + r0) * F + j] =
                    __float2half_rn(gv * (uv / (1.f + expf(-uv))));
            gv = acc[mt][nt][2]; uv = acc[mt][nt][3];
            if (r1 < mrows)
                g_ACT[(size_t)(off + rows0 + r1) * F + j] =
                    __float2half_rn(gv * (uv / (1.f + expf(-uv))));
        }
    }
}

// ---------------- k6: GEMM2  [n_e,F] x Wd[H,F]^T -> Y fp32 ----------------
__global__ void __launch_bounds__(256, 2) k_gemmB(const float* __restrict__ Wd) {
    int e = blockIdx.z;
    int n_e = g_cnt[e];
    int rows0 = blockIdx.x * BM;
    if (rows0 >= n_e) return;
    int off = g_off[e];
    int mrows = min(BM, n_e - rows0);
    int col0 = blockIdx.y * 128;   // H columns
    int tid = threadIdx.x;

    __shared__ __half As[BM * SPITCH];
    __shared__ __half Bs[128 * SPITCH];

    const __half* aptr[2];
    int asmo[2];
#pragma unroll
    for (int it = 0; it < 2; it++) {
        int idx = tid + it * 256;
        int row = idx >> 2, seg = idx & 3;
        asmo[it] = row * SPITCH + seg * 8;
        if (row < mrows)
            aptr[it] = g_ACT + (size_t)(off + rows0 + row) * F + seg * 8;
        else aptr[it] = nullptr;
    }
    const float* bptr[4];
    int bsmo[4];
#pragma unroll
    for (int it = 0; it < 4; it++) {
        int idx = tid + it * 256;
        int row = idx >> 3, seg = idx & 7;
        bsmo[it] = row * SPITCH + seg * 4;
        int h = col0 + row;
        bptr[it] = Wd + ((size_t)e * H + h) * (size_t)F + seg * 4;
    }

    int wid = tid >> 5, lane = tid & 31;
    int wm = wid & 3, wn = wid >> 2;
    int grp = lane >> 2, tg = lane & 3;

    float acc[2][8][4];
#pragma unroll
    for (int mt = 0; mt < 2; mt++)
#pragma unroll
        for (int nt = 0; nt < 8; nt++)
#pragma unroll
            for (int q = 0; q < 4; q++) acc[mt][nt][q] = 0.f;

    uint4 areg[2];
    float4 breg[4];
#pragma unroll
    for (int it = 0; it < 2; it++)
        areg[it] = aptr[it] ? *(const uint4*)(aptr[it]) : make_uint4(0u,0u,0u,0u);
#pragma unroll
    for (int it = 0; it < 4; it++)
        breg[it] = *(const float4*)(bptr[it]);

    for (int kk = 0; kk < F; kk += BK) {
        __syncthreads();
#pragma unroll
        for (int it = 0; it < 2; it++)
            *(uint4*)&As[asmo[it]] = areg[it];
#pragma unroll
        for (int it = 0; it < 4; it++) {
            float4 f = breg[it];
            __half2 lo = __floats2half2_rn(f.x, f.y);
            __half2 hi = __floats2half2_rn(f.z, f.w);
            *(__half2*)&Bs[bsmo[it]]     = lo;
            *(__half2*)&Bs[bsmo[it] + 2] = hi;
        }
        __syncthreads();
        if (kk + BK < F) {
#pragma unroll
            for (int it = 0; it < 2; it++)
                areg[it] = aptr[it] ? *(const uint4*)(aptr[it] + kk + BK) : make_uint4(0u,0u,0u,0u);
#pragma unroll
            for (int it = 0; it < 4; it++)
                breg[it] = *(const float4*)(bptr[it] + kk + BK);
        }
#pragma unroll
        for (int ks = 0; ks < BK; ks += 16) {
            uint32_t afr[2][4];
#pragma unroll
            for (int mt = 0; mt < 2; mt++) {
                int rb = wm * 32 + mt * 16;
                afr[mt][0] = *(const uint32_t*)&As[(rb + grp) * SPITCH + ks + tg * 2];
                afr[mt][1] = *(const uint32_t*)&As[(rb + grp + 8) * SPITCH + ks + tg * 2];
                afr[mt][2] = *(const uint32_t*)&As[(rb + grp) * SPITCH + ks + tg * 2 + 8];
                afr[mt][3] = *(const uint32_t*)&As[(rb + grp + 8) * SPITCH + ks + tg * 2 + 8];
            }
#pragma unroll
            for (int nt = 0; nt < 8; nt++) {
                int baddr = (wn * 64 + nt * 8 + grp) * SPITCH + ks + tg * 2;
                uint32_t b0 = *(const uint32_t*)&Bs[baddr];
                uint32_t b1 = *(const uint32_t*)&Bs[baddr + 8];
                mma16816(acc[0][nt], afr[0], b0, b1);
                mma16816(acc[1][nt], afr[1], b0, b1);
            }
        }
    }
#pragma unroll
    for (int mt = 0; mt < 2; mt++) {
        int r0l = wm * 32 + mt * 16 + grp;
        int r1l = r0l + 8;
#pragma unroll
        for (int nt = 0; nt < 8; nt++) {
            int j = col0 + wn * 64 + nt * 8 + tg * 2;
            if (r0l < mrows) {
                float2 o = make_float2(acc[mt][nt][0], acc[mt][nt][1]);
                *(float2*)&g_Y[(size_t)(off + rows0 + r0l) * H + j] = o;
            }
            if (r1l < mrows) {
                float2 o = make_float2(acc[mt][nt][2], acc[mt][nt][3]);
                *(float2*)&g_Y[(size_t)(off + rows0 + r1l) * H + j] = o;
            }
        }
    }
}

// ---------------- k7: combine + residual ----------------
__global__ void __launch_bounds__(256) k_combine(
    const float* __restrict__ x, float* __restrict__ out)
{
    int t = blockIdx.x, tid = threadIdx.x;
    int s0 = g_tok_slot[t * 2], s1 = g_tok_slot[t * 2 + 1];
    float w0 = g_tok_w[t * 2], w1 = g_tok_w[t * 2 + 1];
    const float4* xv = (const float4*)(x + (size_t)t * H);
    const float4* y0 = (const float4*)(g_Y + (size_t)s0 * H);
    const float4* y1 = (const float4*)(g_Y + (size_t)s1 * H);
    float4* ov = (float4*)(out + (size_t)t * H);
    float4 a = xv[tid], b = y0[tid], c = y1[tid];
    float4 r;
    r.x = a.x + w0 * b.x + w1 * c.x;
    r.y = a.y + w0 * b.y + w1 * c.y;
    r.z = a.z + w0 * b.z + w1 * c.z;
    r.w = a.w + w0 * b.w + w1 * c.w;
    ov[tid] = r;
}

// ---------------- launch ----------------
extern "C" void kernel_launch(void* const* d_in, const int* in_sizes, int n_in,
                              void* d_out, int out_size)
{
    const float* x    = (const float*)d_in[0];
    const float* lnw  = (const float*)d_in[1];
    const float* lnb  = (const float*)d_in[2];
    const float* gw   = (const float*)d_in[3];
    const float* Wg   = (const float*)d_in[4];
    const float* Wu   = (const float*)d_in[5];
    const float* Wd   = (const float*)d_in[6];
    float* out = (float*)d_out;

    k_zero<<<1, 32>>>();
    k_router<<<T, 256>>>(x, lnw, lnb, gw);
    k_scan<<<1, 32>>>(out, out_size);
    k_assign<<<(T * TOPK + 255) / 256, 256>>>();

    // M-tile fastest (blockIdx.x) -> all M-blocks of one weight tile in-flight together
    dim3 gA((T + BM - 1) / BM, F / 64, E);   // (16,64,8)
    k_gemmA<<<gA, 256>>>(Wg, Wu);

    dim3 gB((T + BM - 1) / BM, H / 128, E);  // (16,8,8)
    k_gemmB<<<gB, 256>>>(Wd);

    k_combine<<<T, 256>>>(x, out);
}